// round 1
// baseline (speedup 1.0000x reference)
#include <cuda_runtime.h>
#include <math.h>

// Problem constants
#define NB 128
#define LL 24
#define NN 121
#define DD 121
#define SSN 64
#define NSTEP 6
#define BL 3072            // NB*LL
#define OUT_TOTAL (NSTEP*BL*NN)   // 2,230,272
#define STEP_SLAB (BL*NN)         // 371,712

// K1 config
#define K1_BLOCKS 32
#define K1_ROWS 96         // 32*96 = 3072

// ---------------- device scratch (static, no allocation) ----------------
__device__ float d_gpart[K1_BLOCKS * 968];
__device__ float d_preds[NSTEP * DD];
__device__ __align__(16) float d_Wlift2p[128 * 128];
__device__ __align__(16) float d_Wnet2p [128 * 128];
__device__ __align__(16) float d_Wfc1p  [121 * 128];
__device__ __align__(16) float d_Wfoutp [121 * 128];

// ---------------- pack kernel: pad OUT=121 -> 128 ----------------
__global__ void kpack(const float* __restrict__ lw2, const float* __restrict__ nw2,
                      const float* __restrict__ f1,  const float* __restrict__ fo) {
    int row = blockIdx.x;
    int k = threadIdx.x;           // 128
    if (row < 128) {
        d_Wlift2p[row*128 + k] = (k < 121) ? lw2[row*121 + k] : 0.f;
    } else if (row < 256) {
        int r = row - 128;
        d_Wnet2p[r*128 + k] = (k < 121) ? nw2[r*121 + k] : 0.f;
    } else if (row < 377) {
        int r = row - 256;
        d_Wfc1p[r*128 + k] = (k < 121) ? f1[r*121 + k] : 0.f;
    } else {
        int r = row - 377;
        d_Wfoutp[r*128 + k] = (k < 121) ? fo[r*121 + k] : 0.f;
    }
}

// ---------------- K1: partial GEMM  g[n][j] = sum_bl x[bl,n]*conv_w[bl,j] ----------------
__global__ void k1_gemm(const float* __restrict__ x, const float* __restrict__ cw) {
    __shared__ float cwsm[K1_ROWS * 8];
    int t = threadIdx.x;           // 128 threads
    int r0 = blockIdx.x * K1_ROWS;
    for (int i = t; i < K1_ROWS * 8; i += 128) cwsm[i] = cw[r0*8 + i];
    __syncthreads();
    if (t < 121) {
        float acc[8];
#pragma unroll
        for (int j = 0; j < 8; ++j) acc[j] = 0.f;
#pragma unroll 4
        for (int r = 0; r < K1_ROWS; ++r) {
            float xv = x[(r0 + r)*121 + t];
#pragma unroll
            for (int j = 0; j < 8; ++j) acc[j] = fmaf(xv, cwsm[r*8 + j], acc[j]);
        }
#pragma unroll
        for (int j = 0; j < 8; ++j)
            d_gpart[blockIdx.x*968 + j*121 + t] = acc[j];
    }
}

// ---------------- activations ----------------
#define ACT_NONE 0
#define ACT_RELU 1
#define ACT_TANH 2
#define ACT_SOFTPLUS 3

template<int ACT>
__device__ __forceinline__ float actfn(float v) {
    if (ACT == ACT_RELU) return v > 0.f ? v : 0.f;
    if (ACT == ACT_TANH) return tanhf(v);
    if (ACT == ACT_SOFTPLUS) return v > 20.f ? v : log1pf(expf(v));
    return v;
}

// ---------------- vectorized matvecs (block = 1024 threads) ----------------
// W4: rows of 128 floats (32 float4). out gets 128 values (pad region harmless).
template<int ACT>
__device__ __forceinline__ void matvec128(const float4* __restrict__ W4,
                                          const float* __restrict__ bias, int bias_n,
                                          const float* __restrict__ in, int IN,
                                          float* out, float* red) {
    int tid = threadIdx.x;
    int q = tid & 31, s = tid >> 5;
    if (s < 16) {
        float4 acc = make_float4(0.f, 0.f, 0.f, 0.f);
#pragma unroll 4
        for (int d = s; d < IN; d += 16) {
            float xv = in[d];
            float4 w = W4[d*32 + q];
            acc.x = fmaf(xv, w.x, acc.x);
            acc.y = fmaf(xv, w.y, acc.y);
            acc.z = fmaf(xv, w.z, acc.z);
            acc.w = fmaf(xv, w.w, acc.w);
        }
        ((float4*)red)[s*32 + q] = acc;
    }
    __syncthreads();
    if (tid < 128) {
        float v = 0.f;
#pragma unroll
        for (int ss = 0; ss < 16; ++ss) v += red[ss*128 + tid];
        v += (tid < bias_n) ? bias[tid] : 0.f;
        out[tid] = actfn<ACT>(v);
    }
    __syncthreads();
}

// W4: rows of 64 floats (16 float4). out gets 64 values.
template<int ACT>
__device__ __forceinline__ void matvec64(const float4* __restrict__ W4,
                                         const float* __restrict__ bias,
                                         const float* __restrict__ in, int IN,
                                         float* out, float* red) {
    int tid = threadIdx.x;
    int q = tid & 15, s = tid >> 4;
    if (s < 16) {
        float4 acc = make_float4(0.f, 0.f, 0.f, 0.f);
#pragma unroll 4
        for (int d = s; d < IN; d += 16) {
            float xv = in[d];
            float4 w = W4[d*16 + q];
            acc.x = fmaf(xv, w.x, acc.x);
            acc.y = fmaf(xv, w.y, acc.y);
            acc.z = fmaf(xv, w.z, acc.z);
            acc.w = fmaf(xv, w.w, acc.w);
        }
        ((float4*)red)[s*16 + q] = acc;
    }
    __syncthreads();
    if (tid < 64) {
        float v = 0.f;
#pragma unroll
        for (int ss = 0; ss < 16; ++ss) v += red[ss*64 + tid];
        v += bias[tid];
        out[tid] = actfn<ACT>(v);
    }
    __syncthreads();
}

// ---------------- K2: whole serial chain in one block ----------------
__global__ __launch_bounds__(1024, 1)
void k2_chain(const float* __restrict__ conv_b,
              const float* __restrict__ comp_w1, const float* __restrict__ comp_b1,
              const float* __restrict__ comp_w2, const float* __restrict__ comp_b2,
              const float* __restrict__ adapter_w, const float* __restrict__ adapter_b,
              const float* __restrict__ ln_g, const float* __restrict__ ln_b,
              const float* __restrict__ lift_w1, const float* __restrict__ lift_b1,
              const float* __restrict__ lift_b2,
              const float* __restrict__ net_w1, const float* __restrict__ net_b1,
              const float* __restrict__ net_b2,
              const float* __restrict__ fc1_b,
              const float* __restrict__ fc2_w, const float* __restrict__ fc2_b,
              const float* __restrict__ fc3_w, const float* __restrict__ fc3_b,
              const float* __restrict__ Ag, const float* __restrict__ state_init,
              const float* __restrict__ fcout_b) {
    __shared__ __align__(16) float h_sm[7744];
    __shared__ __align__(16) float red[2048];
    __shared__ float cat[256];      // q in [0..120], lifted in [121..248]
    __shared__ float lifted_h[128];
    __shared__ float net_h[128];
    __shared__ float xt_s[128];
    __shared__ float delta_s[128];
    __shared__ float Bm_s[64];
    __shared__ float Cm_s[64];
    __shared__ float outv[128];
    __shared__ float feat[128];
    __shared__ float compw[320];

    int tid = threadIdx.x;

    // --- 1. reduce GEMM partials -> g in red[n*8+j] ---
    if (tid < 968) {
        int j = tid / 121, n = tid % 121;
        float v = conv_b[j];
#pragma unroll 4
        for (int b = 0; b < K1_BLOCKS; ++b) v += d_gpart[b*968 + tid];
        red[n*8 + j] = v;
    }
    // preload compressor weights (fold the [g,g] duplication: w1[i]+w1[i+8])
    if (tid >= 968) {
        // nothing
    }
    __syncthreads();
    if (tid < 256) compw[tid] = comp_w1[tid] + comp_w1[256 + tid];
    else if (tid < 288) compw[tid] = comp_b1[tid - 256];
    else if (tid < 320) compw[tid] = comp_w2[tid - 288];
    __syncthreads();

    // --- 2. feature compressor -> feat[n] ---
    if (tid < 121) {
        float gv[8];
#pragma unroll
        for (int j = 0; j < 8; ++j) gv[j] = red[tid*8 + j];
        float f = comp_b2[0];
#pragma unroll 4
        for (int k = 0; k < 32; ++k) {
            float hh = compw[256 + k];
#pragma unroll
            for (int i = 0; i < 8; ++i) hh = fmaf(gv[i], compw[i*32 + k], hh);
            hh = hh > 0.f ? hh : 0.01f * hh;
            f = fmaf(hh, compw[288 + k], f);
        }
        feat[tid] = f;
    }
    __syncthreads();

    // --- 3. adapter matvec (one-time, scalar) ---
    if (tid < 121) {
        float v = adapter_b[tid];
        for (int n = 0; n < 121; ++n) v = fmaf(feat[n], adapter_w[n*121 + tid], v);
        outv[tid] = v;
    }
    __syncthreads();

    // --- 4. layernorm -> q = cat[0..120] ---
    {
        float zv = (tid < 121) ? outv[tid] : 0.f;
        red[tid] = zv;
        red[1024 + tid] = zv * zv;
        __syncthreads();
        for (int off = 512; off > 0; off >>= 1) {
            if (tid < off) {
                red[tid] += red[tid + off];
                red[1024 + tid] += red[1024 + tid + off];
            }
            __syncthreads();
        }
        float mu = red[0] * (1.f / 121.f);
        float var = red[1024] * (1.f / 121.f) - mu * mu;
        float rstd = rsqrtf(var + 1e-5f);
        if (tid < 121) cat[tid] = (outv[tid] - mu) * rstd * ln_g[tid] + ln_b[tid];
    }
    // --- 5. init state h from state_init ---
    for (int e = tid; e < 7744; e += 1024) h_sm[e] = state_init[e];
    __syncthreads();

    // --- 6. 7 serial mamba iterations (iter 0 = warmup: out discarded, q stays) ---
    for (int it = 0; it < 7; ++it) {
        matvec128<ACT_RELU>((const float4*)lift_w1, lift_b1, 128, cat, 121, lifted_h, red);
        matvec128<ACT_TANH>((const float4*)d_Wlift2p, lift_b2, 121, lifted_h, 128, cat + 121, red);
        matvec128<ACT_RELU>((const float4*)net_w1, net_b1, 128, cat, 242, net_h, red);
        matvec128<ACT_NONE>((const float4*)d_Wnet2p, net_b2, 121, net_h, 128, xt_s, red);
        matvec128<ACT_SOFTPLUS>((const float4*)d_Wfc1p, fc1_b, 121, xt_s, 121, delta_s, red);
        matvec64<ACT_NONE>((const float4*)fc2_w, fc2_b, xt_s, 121, Bm_s, red);
        matvec64<ACT_NONE>((const float4*)fc3_w, fc3_b, xt_s, 121, Cm_s, red);

        // state update + out[d] = sum_n Cm[n]*h_new[d][n]
        if (tid < 968) {
            int d = tid >> 3, s = tid & 7;
            float dl = delta_s[d];
            float xd = xt_s[d] * dl;
            float po = 0.f;
            int base = d*64 + s*8;
            const float4* A4 = (const float4*)(Ag + base);
            float4 a0 = A4[0], a1 = A4[1];
            float av[8] = {a0.x, a0.y, a0.z, a0.w, a1.x, a1.y, a1.z, a1.w};
#pragma unroll
            for (int j = 0; j < 8; ++j) {
                float z = dl * av[j];
                float cel = z > 0.f ? z : expm1f(z);
                float dA = expf(-cel);
                float hn = fmaf(dA, h_sm[base + j], xd * Bm_s[s*8 + j]);
                h_sm[base + j] = hn;
                po = fmaf(Cm_s[s*8 + j], hn, po);
            }
            red[tid] = po;
        }
        __syncthreads();
        if (tid < 121) {
            float v = 0.f;
#pragma unroll
            for (int s2 = 0; s2 < 8; ++s2) v += red[tid*8 + s2];
            outv[tid] = v;
        }
        __syncthreads();

        if (it > 0) {
            // pred = out @ fcout + b ; q = pred ; store pred
            matvec128<ACT_NONE>((const float4*)d_Wfoutp, fcout_b, 121, outv, 121, cat, red);
            if (tid < 121) d_preds[(it - 1)*121 + tid] = cat[tid];
        }
        // it == 0: q (cat[0..120]) untouched -> stays z0, matching reference
    }
}

// ---------------- K3: broadcast preds into the full output ----------------
__global__ void k3_bcast(float* __restrict__ out) {
    int i = blockIdx.x * blockDim.x + threadIdx.x;
    if (i < OUT_TOTAL) {
        int step = i / STEP_SLAB;
        int d = i % 121;
        out[i] = d_preds[step*121 + d];
    }
}

// ---------------- launch ----------------
extern "C" void kernel_launch(void* const* d_in, const int* in_sizes, int n_in,
                              void* d_out, int out_size) {
    const float* x          = (const float*)d_in[0];
    // d_in[1] edge_index, d_in[2] edge_attr: unused (ChebConv K=1 ignores edges)
    const float* conv_w     = (const float*)d_in[3];
    const float* conv_b     = (const float*)d_in[4];
    const float* comp_w1    = (const float*)d_in[5];
    const float* comp_b1    = (const float*)d_in[6];
    const float* comp_w2    = (const float*)d_in[7];
    const float* comp_b2    = (const float*)d_in[8];
    const float* adapter_w  = (const float*)d_in[9];
    const float* adapter_b  = (const float*)d_in[10];
    const float* ln_g       = (const float*)d_in[11];
    const float* ln_b       = (const float*)d_in[12];
    const float* lift_w1    = (const float*)d_in[13];
    const float* lift_b1    = (const float*)d_in[14];
    const float* lift_w2    = (const float*)d_in[15];
    const float* lift_b2    = (const float*)d_in[16];
    const float* net_w1     = (const float*)d_in[17];
    const float* net_b1     = (const float*)d_in[18];
    const float* net_w2     = (const float*)d_in[19];
    const float* net_b2     = (const float*)d_in[20];
    const float* fc1_w      = (const float*)d_in[21];
    const float* fc1_b      = (const float*)d_in[22];
    const float* fc2_w      = (const float*)d_in[23];
    const float* fc2_b      = (const float*)d_in[24];
    const float* fc3_w      = (const float*)d_in[25];
    const float* fc3_b      = (const float*)d_in[26];
    const float* A          = (const float*)d_in[27];
    const float* state_init = (const float*)d_in[28];
    const float* fcout_w    = (const float*)d_in[29];
    const float* fcout_b    = (const float*)d_in[30];

    (void)in_sizes; (void)n_in;

    // pad weight layouts for float4 loads
    kpack<<<498, 128>>>(lift_w2, net_w2, fc1_w, fcout_w);

    // the only data-dependent GEMM: g = x^T @ conv_w (partials)
    k1_gemm<<<K1_BLOCKS, 128>>>(x, conv_w);

    // serial chain on one block
    k2_chain<<<1, 1024>>>(conv_b, comp_w1, comp_b1, comp_w2, comp_b2,
                          adapter_w, adapter_b, ln_g, ln_b,
                          lift_w1, lift_b1, lift_b2,
                          net_w1, net_b1, net_b2,
                          fc1_b, fc2_w, fc2_b, fc3_w, fc3_b,
                          A, state_init, fcout_b);

    // broadcast 6 vectors of 121 into (6,128,24,121)
    int total = out_size;
    int blocks = (total + 1023) / 1024;
    k3_bcast<<<blocks, 1024>>>((float*)d_out);
}

// round 2
// speedup vs baseline: 1.5103x; 1.5103x over previous
#include <cuda_runtime.h>
#include <cuda_fp16.h>
#include <math.h>

// Problem constants
#define NB 128
#define LL 24
#define NN 121
#define DD 121
#define SSN 64
#define NSTEP 6
#define BL 3072
#define OUT_TOTAL (NSTEP*BL*NN)   // 2,230,272
#define STEP_SLAB (BL*NN)         // 371,712

// K1 config
#define K1_BLOCKS 32
#define K1_ROWS 96

// fp16 smem-resident weight pack layout (half element offsets)
#define HS_LIFT1 0          // 121*128
#define HS_LIFT2 15488      // 128*128
#define HS_NET1  31872      // 242*128
#define HS_NET2  62848      // 128*128
#define HS_FC1   79232      // 121*128
#define HS_TOTAL 94720      // halfs -> 189,440 bytes

// dynamic smem byte offsets inside k2
#define SM_RED   189440     // float[4096] = 16384 B
#define SM_CAT   205824     // float[256]
#define SM_LIFT  206848     // float[128]
#define SM_NETH  207360     // float[128]
#define SM_XT    207872     // float[128]
#define SM_DELTA 208384     // float[128]
#define SM_BC    208896     // float[128]  (Bm | Cm)
#define SM_OUTV  209408     // float[128]
#define SM_FEAT  209920     // float[128]
#define SM_COMPW 210432     // float[320]
#define SMEM_BYTES 211712

// ---------------- device scratch (static, no allocation) ----------------
__device__ float d_gpart[K1_BLOCKS * 968];
__device__ float d_preds[NSTEP * DD];
__device__ __align__(16) __half d_hsm[HS_TOTAL];      // smem-resident pack
__device__ __align__(16) __half d_h_fout[121 * 128];  // streamed
__device__ __align__(16) __half d_h_fc23[121 * 128];  // streamed (fc2 | fc3)

// ---------------- pack kernel: fp32 -> fp16, pad cols to 128 ----------------
__global__ void kpack(const float* __restrict__ lw1, const float* __restrict__ lw2,
                      const float* __restrict__ nw1, const float* __restrict__ nw2,
                      const float* __restrict__ f1,  const float* __restrict__ fo,
                      const float* __restrict__ f2,  const float* __restrict__ f3) {
    int row = blockIdx.x;
    int k = threadIdx.x;  // 128
    if (row < 121) {                       // lift_w1 (121 x 128)
        d_hsm[HS_LIFT1 + row*128 + k] = __float2half_rn(lw1[row*128 + k]);
    } else if (row < 249) {                // lift_w2 (128 x 121 -> pad)
        int r = row - 121;
        d_hsm[HS_LIFT2 + r*128 + k] = __float2half_rn(k < 121 ? lw2[r*121 + k] : 0.f);
    } else if (row < 491) {                // net_w1 (242 x 128)
        int r = row - 249;
        d_hsm[HS_NET1 + r*128 + k] = __float2half_rn(nw1[r*128 + k]);
    } else if (row < 619) {                // net_w2 (128 x 121 -> pad)
        int r = row - 491;
        d_hsm[HS_NET2 + r*128 + k] = __float2half_rn(k < 121 ? nw2[r*121 + k] : 0.f);
    } else if (row < 740) {                // fc1_w (121 x 121 -> pad)
        int r = row - 619;
        d_hsm[HS_FC1 + r*128 + k] = __float2half_rn(k < 121 ? f1[r*121 + k] : 0.f);
    } else if (row < 861) {                // fcout_w (121 x 121 -> pad)
        int r = row - 740;
        d_h_fout[r*128 + k] = __float2half_rn(k < 121 ? fo[r*121 + k] : 0.f);
    } else {                               // fc2 | fc3 (121 x (64|64))
        int r = row - 861;
        float v = (k < 64) ? f2[r*64 + k] : f3[r*64 + (k - 64)];
        d_h_fc23[r*128 + k] = __float2half_rn(v);
    }
}

// ---------------- K1: partial GEMM  g[n][j] = sum_bl x[bl,n]*conv_w[bl,j] ----------------
__global__ void k1_gemm(const float* __restrict__ x, const float* __restrict__ cw) {
    __shared__ float cwsm[K1_ROWS * 8];
    int t = threadIdx.x;  // 128
    int r0 = blockIdx.x * K1_ROWS;
    for (int i = t; i < K1_ROWS * 8; i += 128) cwsm[i] = cw[r0*8 + i];
    __syncthreads();
    if (t < 121) {
        float acc[8];
#pragma unroll
        for (int j = 0; j < 8; ++j) acc[j] = 0.f;
#pragma unroll 4
        for (int r = 0; r < K1_ROWS; ++r) {
            float xv = x[(r0 + r)*121 + t];
#pragma unroll
            for (int j = 0; j < 8; ++j) acc[j] = fmaf(xv, cwsm[r*8 + j], acc[j]);
        }
#pragma unroll
        for (int j = 0; j < 8; ++j)
            d_gpart[blockIdx.x*968 + j*121 + t] = acc[j];
    }
}

// ---------------- activations ----------------
#define ACT_NONE 0
#define ACT_RELU 1
#define ACT_TANH 2
#define ACT_SOFTPLUS 3

template<int ACT>
__device__ __forceinline__ float actfn(float v) {
    if (ACT == ACT_RELU) return v > 0.f ? v : 0.f;
    if (ACT == ACT_TANH) return tanhf(v);
    if (ACT == ACT_SOFTPLUS) return v > 20.f ? v : log1pf(expf(v));
    return v;
}

// ---------------- fp16-weight matvec: 128 outputs, 32 slices, 1024 thr ----------------
// W2: rows of 128 halfs = 32 uint2 per row. Thread q owns outputs 4q..4q+3.
template<int ACT>
__device__ __forceinline__ void mv128h(const uint2* __restrict__ W2,
                                       const float* __restrict__ bias, int bias_n,
                                       const float* __restrict__ in, int IN,
                                       float* __restrict__ out, float* __restrict__ red) {
    int tid = threadIdx.x;
    int q = tid & 31, s = tid >> 5;       // q: 0..31, s: 0..31
    float4 acc = make_float4(0.f, 0.f, 0.f, 0.f);
#pragma unroll 4
    for (int d = s; d < IN; d += 32) {
        float xv = in[d];
        uint2 w = W2[d*32 + q];
        float2 w01 = __half22float2(*(const __half2*)&w.x);
        float2 w23 = __half22float2(*(const __half2*)&w.y);
        acc.x = fmaf(xv, w01.x, acc.x);
        acc.y = fmaf(xv, w01.y, acc.y);
        acc.z = fmaf(xv, w23.x, acc.z);
        acc.w = fmaf(xv, w23.y, acc.w);
    }
    ((float4*)red)[s*32 + q] = acc;
    __syncthreads();
    if (tid < 128) {
        float v = 0.f;
#pragma unroll
        for (int ss = 0; ss < 32; ++ss) v += red[ss*128 + tid];
        v += (tid < bias_n) ? bias[tid] : 0.f;
        out[tid] = actfn<ACT>(v);
    }
    __syncthreads();
}

// ---------------- K2: whole serial chain in one block ----------------
__global__ __launch_bounds__(1024, 1)
void k2_chain(const float* __restrict__ conv_b,
              const float* __restrict__ comp_w1, const float* __restrict__ comp_b1,
              const float* __restrict__ comp_w2, const float* __restrict__ comp_b2,
              const float* __restrict__ adapter_w, const float* __restrict__ adapter_b,
              const float* __restrict__ ln_g, const float* __restrict__ ln_b,
              const float* __restrict__ lift_b1, const float* __restrict__ lift_b2,
              const float* __restrict__ net_b1, const float* __restrict__ net_b2,
              const float* __restrict__ fc1_b,
              const float* __restrict__ fc2_b, const float* __restrict__ fc3_b,
              const float* __restrict__ Ag, const float* __restrict__ state_init,
              const float* __restrict__ fcout_b) {
    extern __shared__ __align__(16) unsigned char smraw[];
    float* red    = (float*)(smraw + SM_RED);
    float* cat    = (float*)(smraw + SM_CAT);
    float* lifted = (float*)(smraw + SM_LIFT);
    float* net_h  = (float*)(smraw + SM_NETH);
    float* xt_s   = (float*)(smraw + SM_XT);
    float* delta_s= (float*)(smraw + SM_DELTA);
    float* bc     = (float*)(smraw + SM_BC);
    float* outv   = (float*)(smraw + SM_OUTV);
    float* feat   = (float*)(smraw + SM_FEAT);
    float* compw  = (float*)(smraw + SM_COMPW);

    const uint2* W_lift1 = (const uint2*)(smraw);
    const uint2* W_lift2 = (const uint2*)(smraw + HS_LIFT2*2);
    const uint2* W_net1  = (const uint2*)(smraw + HS_NET1*2);
    const uint2* W_net2  = (const uint2*)(smraw + HS_NET2*2);
    const uint2* W_fc1   = (const uint2*)(smraw + HS_FC1*2);
    const uint2* W_fc23  = (const uint2*)d_h_fc23;   // streamed (global)
    const uint2* W_fout  = (const uint2*)d_h_fout;   // streamed (global)

    int tid = threadIdx.x;

    // --- 0. load resident weight pack into smem (189,440 B = 11,840 uint4) ---
    {
        const uint4* src = (const uint4*)d_hsm;
        uint4* dst = (uint4*)smraw;
#pragma unroll 4
        for (int i = tid; i < HS_TOTAL/8; i += 1024) dst[i] = src[i];
    }

    // --- 1. reduce GEMM partials -> g in red[n*8+j] ---
    if (tid < 968) {
        int j = tid / 121, n = tid % 121;
        float v = conv_b[j];
#pragma unroll 4
        for (int b = 0; b < K1_BLOCKS; ++b) v += d_gpart[b*968 + tid];
        red[n*8 + j] = v;
    }
    __syncthreads();
    if (tid < 256) compw[tid] = comp_w1[tid] + comp_w1[256 + tid];
    else if (tid < 288) compw[tid] = comp_b1[tid - 256];
    else if (tid < 320) compw[tid] = comp_w2[tid - 288];
    __syncthreads();

    // --- 2. feature compressor -> feat[n] ---
    if (tid < 121) {
        float gv[8];
#pragma unroll
        for (int j = 0; j < 8; ++j) gv[j] = red[tid*8 + j];
        float f = comp_b2[0];
#pragma unroll 4
        for (int k = 0; k < 32; ++k) {
            float hh = compw[256 + k];
#pragma unroll
            for (int i = 0; i < 8; ++i) hh = fmaf(gv[i], compw[i*32 + k], hh);
            hh = hh > 0.f ? hh : 0.01f * hh;
            f = fmaf(hh, compw[288 + k], f);
        }
        feat[tid] = f;
    }
    __syncthreads();

    // --- 3. adapter matvec (one-time) ---
    if (tid < 121) {
        float v = adapter_b[tid];
        for (int n = 0; n < 121; ++n) v = fmaf(feat[n], adapter_w[n*121 + tid], v);
        outv[tid] = v;
    }
    __syncthreads();

    // --- 4. layernorm -> q = cat[0..120] ---
    {
        float zv = (tid < 121) ? outv[tid] : 0.f;
        red[tid] = zv;
        red[1024 + tid] = zv * zv;
        __syncthreads();
        for (int off = 512; off > 0; off >>= 1) {
            if (tid < off) {
                red[tid] += red[tid + off];
                red[1024 + tid] += red[1024 + tid + off];
            }
            __syncthreads();
        }
        float mu = red[0] * (1.f / 121.f);
        float var = red[1024] * (1.f / 121.f) - mu * mu;
        float rstd = rsqrtf(var + 1e-5f);
        if (tid < 121) cat[tid] = (outv[tid] - mu) * rstd * ln_g[tid] + ln_b[tid];
    }

    // --- 5. state h in registers: thread tid<968 holds h[d= tid>>3][ (tid&7)*8 .. +7 ] ---
    float h[8];
    int sd = tid >> 3, s8 = tid & 7;
    int hbase = sd * 64 + s8 * 8;
    if (tid < 968) {
        float4 h0 = *(const float4*)(state_init + hbase);
        float4 h1 = *(const float4*)(state_init + hbase + 4);
        h[0]=h0.x; h[1]=h0.y; h[2]=h0.z; h[3]=h0.w;
        h[4]=h1.x; h[5]=h1.y; h[6]=h1.z; h[7]=h1.w;
    }
    __syncthreads();

    // --- 6. 7 serial mamba iterations (iter 0 = warmup) ---
    for (int it = 0; it < 7; ++it) {
        mv128h<ACT_RELU>(W_lift1, lift_b1, 128, cat, 121, lifted, red);
        mv128h<ACT_TANH>(W_lift2, lift_b2, 121, lifted, 128, cat + 121, red);
        mv128h<ACT_RELU>(W_net1,  net_b1,  128, cat, 242, net_h, red);
        mv128h<ACT_NONE>(W_net2,  net_b2,  121, net_h, 128, xt_s, red);
        mv128h<ACT_SOFTPLUS>(W_fc1, fc1_b, 121, xt_s, 121, delta_s, red);
        // fused Bm|Cm: outputs 0..63 = fc2 (+fc2_b), 64..127 = fc3 (+fc3_b)
        {
            int q = tid & 31, s = tid >> 5;
            float4 acc = make_float4(0.f, 0.f, 0.f, 0.f);
#pragma unroll 4
            for (int d = s; d < 121; d += 32) {
                float xv = xt_s[d];
                uint2 w = W_fc23[d*32 + q];
                float2 w01 = __half22float2(*(const __half2*)&w.x);
                float2 w23 = __half22float2(*(const __half2*)&w.y);
                acc.x = fmaf(xv, w01.x, acc.x);
                acc.y = fmaf(xv, w01.y, acc.y);
                acc.z = fmaf(xv, w23.x, acc.z);
                acc.w = fmaf(xv, w23.y, acc.w);
            }
            ((float4*)red)[s*32 + q] = acc;
            __syncthreads();
            if (tid < 128) {
                float v = 0.f;
#pragma unroll
                for (int ss = 0; ss < 32; ++ss) v += red[ss*128 + tid];
                v += (tid < 64) ? fc2_b[tid] : fc3_b[tid - 64];
                bc[tid] = v;
            }
            __syncthreads();
        }

        // state update + partial out
        if (tid < 968) {
            float dl = delta_s[sd];
            float xd = xt_s[sd] * dl;
            float po = 0.f;
            const float4* A4 = (const float4*)(Ag + hbase);
            float4 a0 = A4[0], a1 = A4[1];
            float av[8] = {a0.x, a0.y, a0.z, a0.w, a1.x, a1.y, a1.z, a1.w};
#pragma unroll
            for (int j = 0; j < 8; ++j) {
                float z = dl * av[j];
                float cel = z > 0.f ? z : expm1f(z);
                float dA = expf(-cel);
                float hn = fmaf(dA, h[j], xd * bc[s8*8 + j]);       // Bm = bc[0..63]
                h[j] = hn;
                po = fmaf(bc[64 + s8*8 + j], hn, po);               // Cm = bc[64..127]
            }
            red[tid] = po;
        }
        __syncthreads();
        if (tid < 121) {
            float v = 0.f;
#pragma unroll
            for (int s2 = 0; s2 < 8; ++s2) v += red[tid*8 + s2];
            outv[tid] = v;
        }
        __syncthreads();

        if (it > 0) {
            mv128h<ACT_NONE>(W_fout, fcout_b, 121, outv, 121, cat, red);
            if (tid < 121) d_preds[(it - 1)*121 + tid] = cat[tid];
        }
        // it == 0: q (cat[0..120]) untouched -> stays z0
    }
}

// ---------------- K3: vectorized broadcast into full output ----------------
__global__ __launch_bounds__(512)
void k3_bcast(float4* __restrict__ out) {
    __shared__ float sp[NSTEP * 121];
    int tid = threadIdx.x;
    if (tid < NSTEP * 121) sp[tid] = d_preds[tid];
    __syncthreads();
    int i4 = blockIdx.x * 512 + tid;
    int i = i4 << 2;
    if (i < OUT_TOTAL) {
        int step = i / STEP_SLAB;
        int rem = i - step * STEP_SLAB;
        int d = rem % 121;
        const float* p = sp + step * 121;
        float4 v;
        v.x = p[d]; d = (d + 1 == 121) ? 0 : d + 1;
        v.y = p[d]; d = (d + 1 == 121) ? 0 : d + 1;
        v.z = p[d]; d = (d + 1 == 121) ? 0 : d + 1;
        v.w = p[d];
        out[i4] = v;
    }
}

// ---------------- launch ----------------
extern "C" void kernel_launch(void* const* d_in, const int* in_sizes, int n_in,
                              void* d_out, int out_size) {
    const float* x          = (const float*)d_in[0];
    const float* conv_w     = (const float*)d_in[3];
    const float* conv_b     = (const float*)d_in[4];
    const float* comp_w1    = (const float*)d_in[5];
    const float* comp_b1    = (const float*)d_in[6];
    const float* comp_w2    = (const float*)d_in[7];
    const float* comp_b2    = (const float*)d_in[8];
    const float* adapter_w  = (const float*)d_in[9];
    const float* adapter_b  = (const float*)d_in[10];
    const float* ln_g       = (const float*)d_in[11];
    const float* ln_b       = (const float*)d_in[12];
    const float* lift_w1    = (const float*)d_in[13];
    const float* lift_b1    = (const float*)d_in[14];
    const float* lift_w2    = (const float*)d_in[15];
    const float* lift_b2    = (const float*)d_in[16];
    const float* net_w1     = (const float*)d_in[17];
    const float* net_b1     = (const float*)d_in[18];
    const float* net_w2     = (const float*)d_in[19];
    const float* net_b2     = (const float*)d_in[20];
    const float* fc1_w      = (const float*)d_in[21];
    const float* fc1_b      = (const float*)d_in[22];
    const float* fc2_w      = (const float*)d_in[23];
    const float* fc2_b      = (const float*)d_in[24];
    const float* fc3_w      = (const float*)d_in[25];
    const float* fc3_b      = (const float*)d_in[26];
    const float* A          = (const float*)d_in[27];
    const float* state_init = (const float*)d_in[28];
    const float* fcout_w    = (const float*)d_in[29];
    const float* fcout_b    = (const float*)d_in[30];
    (void)in_sizes; (void)n_in;

    static int smem_set = 0;
    if (!smem_set) {
        cudaFuncSetAttribute(k2_chain, cudaFuncAttributeMaxDynamicSharedMemorySize, SMEM_BYTES);
        smem_set = 1;
    }

    // fp16 weight packs
    kpack<<<982, 128>>>(lift_w1, lift_w2, net_w1, net_w2, fc1_w, fcout_w, fc2_w, fc3_w);

    // data-dependent GEMM partials
    k1_gemm<<<K1_BLOCKS, 128>>>(x, conv_w);

    // serial chain on one block (smem-resident fp16 weights)
    k2_chain<<<1, 1024, SMEM_BYTES>>>(conv_b, comp_w1, comp_b1, comp_w2, comp_b2,
                                      adapter_w, adapter_b, ln_g, ln_b,
                                      lift_b1, lift_b2, net_b1, net_b2,
                                      fc1_b, fc2_b, fc3_b,
                                      A, state_init, fcout_b);

    // broadcast 6 vectors of 121 into (6,128,24,121)
    int blocks = (out_size/4 + 511) / 512;
    k3_bcast<<<blocks, 512>>>((float4*)d_out);
}